// round 4
// baseline (speedup 1.0000x reference)
#include <cuda_runtime.h>
#include <math.h>

#define NN 20000
#define EE 320000
#define ET 340000      // EE + NN self loops
#define FIN 128
#define D1 512         // HEADS*HID
#define HEADS 8
#define HID 64
#define NC 10
#define NG 64

// -------- scratch (device globals; no allocations allowed) --------
__device__ float g_aggx[(size_t)NN * HEADS * FIN];  // per-head aggregated x (normalized)
__device__ float g_h1act[(size_t)NN * D1];          // elu(aggx @ W1 + b1)
__device__ float g_va[FIN * HEADS * 2];             // [c][h] src then dst halves
__device__ float g_asrc1[NN * HEADS];
__device__ float g_adst1[NN * HEADS];
__device__ float g_h2[NN * NC];
__device__ float g_asrc2[NN];
__device__ float g_adst2[NN];
__device__ float g_agg2[NN * NC];
__device__ int   g_counts[NN];
__device__ int   g_rowptr[NN + 1];
__device__ int   g_wptr[NN];
__device__ int   g_csrc[ET];

__device__ __forceinline__ float wredsum(float v) {
    #pragma unroll
    for (int o = 16; o; o >>= 1) v += __shfl_xor_sync(0xffffffffu, v, o);
    return v;
}

// -------- CSR build --------
__global__ void zero_counts_kernel() {
    int i = blockIdx.x * blockDim.x + threadIdx.x;
    if (i < NN) g_counts[i] = 0;
}

__global__ void count_kernel(const int* __restrict__ ei) {
    int e = blockIdx.x * blockDim.x + threadIdx.x;
    if (e >= ET) return;
    int dst = (e < EE) ? ei[EE + e] : (e - EE);
    atomicAdd(&g_counts[dst], 1);
}

__global__ void scan_kernel() {
    __shared__ int sh[1024];
    int t = threadIdx.x;
    const int CH = (NN + 1023) / 1024;
    int base = t * CH;
    int s = 0;
    for (int i = 0; i < CH; i++) {
        int idx = base + i;
        if (idx < NN) s += g_counts[idx];
    }
    sh[t] = s;
    __syncthreads();
    for (int off = 1; off < 1024; off <<= 1) {
        int v = (t >= off) ? sh[t - off] : 0;
        __syncthreads();
        sh[t] += v;
        __syncthreads();
    }
    int run = sh[t] - s;
    for (int i = 0; i < CH; i++) {
        int idx = base + i;
        if (idx < NN) {
            g_rowptr[idx] = run;
            g_wptr[idx] = run;
            run += g_counts[idx];
        }
    }
    if (t == 1023) g_rowptr[NN] = sh[1023];
}

__global__ void scatter_kernel(const int* __restrict__ ei) {
    int e = blockIdx.x * blockDim.x + threadIdx.x;
    if (e >= ET) return;
    int src, dst;
    if (e < EE) { src = ei[e]; dst = ei[EE + e]; }
    else        { src = e - EE; dst = src; }
    int pos = atomicAdd(&g_wptr[dst], 1);
    g_csrc[pos] = src;
}

// -------- va: folded attention vectors  va_src[c][h] = sum_j W1[c, h*64+j]*a_src[h][j] --------
__global__ void va_kernel(const float* __restrict__ W1,
                          const float* __restrict__ asv,
                          const float* __restrict__ adv) {
    int h = blockIdx.x;          // 8 blocks
    int c = threadIdx.x;         // 128
    __shared__ float sa[HID], sd[HID];
    if (c < HID) { sa[c] = asv[h * HID + c]; sd[c] = adv[h * HID + c]; }
    __syncthreads();
    const float* wp = &W1[(size_t)c * D1 + h * HID];
    float s = 0.f, d = 0.f;
    #pragma unroll 8
    for (int j = 0; j < HID; j++) {
        float w = wp[j];
        s += w * sa[j];
        d += w * sd[j];
    }
    g_va[c * HEADS + h] = s;
    g_va[FIN * HEADS + c * HEADS + h] = d;
}

// -------- per-node attention logits: asrc1[n][h] = x[n] . va_src[:,h] --------
__global__ void coefx_kernel(const float* __restrict__ X) {
    __shared__ float vs[FIN * HEADS], vd[FIN * HEADS];
    int t = threadIdx.x;   // 256
    for (int i = t; i < FIN * HEADS; i += 256) {
        vs[i] = g_va[i];
        vd[i] = g_va[FIN * HEADS + i];
    }
    __syncthreads();
    int n = blockIdx.x * 8 + (t >> 5);
    if (n >= NN) return;
    int lane = t & 31;
    float4 xv = *(const float4*)&X[(size_t)n * FIN + lane * 4];
    float s[HEADS], d[HEADS];
    #pragma unroll
    for (int h = 0; h < HEADS; h++) { s[h] = 0.f; d[h] = 0.f; }
    #pragma unroll
    for (int q = 0; q < 4; q++) {
        int c = lane * 4 + q;
        float xq = (q == 0) ? xv.x : (q == 1) ? xv.y : (q == 2) ? xv.z : xv.w;
        #pragma unroll
        for (int h = 0; h < HEADS; h++) {
            s[h] += xq * vs[c * HEADS + h];
            d[h] += xq * vd[c * HEADS + h];
        }
    }
    #pragma unroll
    for (int h = 0; h < HEADS; h++) {
        s[h] = wredsum(s[h]);
        d[h] = wredsum(d[h]);
    }
    if (lane == 0) {
        #pragma unroll
        for (int h = 0; h < HEADS; h++) {
            g_asrc1[n * HEADS + h] = s[h];
            g_adst1[n * HEADS + h] = d[h];
        }
    }
}

// -------- layer-1 softmax-weighted aggregation of RAW x rows --------
// aggx[d][h][c] = sum_e w_e^h * x[src_e][c] / sum_e w_e^h
__global__ void agg1x_kernel(const float* __restrict__ X) {
    int d = blockIdx.x;
    int t = threadIdx.x;   // 128, thread t owns channel c = t
    __shared__ float sadst[8], salpha[128], sinv[8];
    __shared__ int ssrc[16];
    int beg = g_rowptr[d];
    int deg = g_rowptr[d + 1] - beg;
    if (t < 8) sadst[t] = g_adst1[d * 8 + t];
    float acc[8];
    #pragma unroll
    for (int h = 0; h < 8; h++) acc[h] = 0.f;
    float wpart = 0.f;

    for (int base = 0; base < deg; base += 16) {
        int cn = min(16, deg - base);
        __syncthreads();
        if (t < cn) ssrc[t] = g_csrc[beg + base + t];
        if (t < cn * 8) {
            int i = t >> 3, h = t & 7;
            float e = g_asrc1[g_csrc[beg + base + i] * 8 + h] + sadst[h];
            e = e > 0.f ? e : 0.2f * e;
            float w = __expf(e);
            salpha[t] = w;
            wpart += w;
        }
        __syncthreads();
        #pragma unroll 4
        for (int i = 0; i < cn; i++) {
            float xv = X[(size_t)ssrc[i] * FIN + t];
            float4 a0 = *(const float4*)&salpha[i * 8];
            float4 a1 = *(const float4*)&salpha[i * 8 + 4];
            acc[0] += a0.x * xv; acc[1] += a0.y * xv;
            acc[2] += a0.z * xv; acc[3] += a0.w * xv;
            acc[4] += a1.x * xv; acc[5] += a1.y * xv;
            acc[6] += a1.z * xv; acc[7] += a1.w * xv;
        }
    }
    __syncthreads();
    salpha[t] = wpart;
    __syncthreads();
    if (t < 8) {
        float s = 0.f;
        #pragma unroll
        for (int j = 0; j < 16; j++) s += salpha[t + 8 * j];
        sinv[t] = 1.f / (s + 1e-16f);
    }
    __syncthreads();
    float* op = &g_aggx[(size_t)d * (HEADS * FIN)];
    #pragma unroll
    for (int h = 0; h < 8; h++) op[h * FIN + t] = acc[h] * sinv[h];
}

// -------- per-head GEMM: h1act[:, h*64:(h+1)*64] = elu(aggx[:,h,:] @ W1[:, h*64:..] + b1) --------
// BM=64, BN=64(=head), BK=64 x2, 256 threads, 4x4 microtile
__global__ void gemmh_kernel(const float* __restrict__ W1,
                             const float* __restrict__ b1) {
    __shared__ float As[64][68];
    __shared__ float Bs[64][64];
    __shared__ float sb[64];
    int t = threadIdx.x;
    int h = blockIdx.x;
    int m0 = blockIdx.y * 64;
    if (t < 64) sb[t] = b1[h * HID + t];
    int tm = (t >> 4) << 2;
    int tn = (t & 15) << 2;
    float acc[4][4];
    #pragma unroll
    for (int i = 0; i < 4; i++)
        #pragma unroll
        for (int j = 0; j < 4; j++) acc[i][j] = 0.f;

    for (int k0 = 0; k0 < FIN; k0 += 64) {
        int kk = t & 63;
        #pragma unroll
        for (int p = 0; p < 16; p++) {
            int rr = (t >> 6) + p * 4;
            int row = m0 + rr;
            float v = (row < NN)
                ? g_aggx[(size_t)row * (HEADS * FIN) + h * FIN + k0 + kk] : 0.f;
            As[kk][rr] = v;
        }
        #pragma unroll
        for (int p = 0; p < 4; p++) {
            int id = t + p * 256;
            int bk = id >> 4, nv = id & 15;
            float4 v = *(const float4*)&W1[(size_t)(k0 + bk) * D1 + h * HID + (nv << 2)];
            *(float4*)&Bs[bk][nv << 2] = v;
        }
        __syncthreads();
        #pragma unroll 16
        for (int k = 0; k < 64; k++) {
            float4 a = *(const float4*)&As[k][tm];
            float4 b = *(const float4*)&Bs[k][tn];
            acc[0][0] += a.x * b.x; acc[0][1] += a.x * b.y; acc[0][2] += a.x * b.z; acc[0][3] += a.x * b.w;
            acc[1][0] += a.y * b.x; acc[1][1] += a.y * b.y; acc[1][2] += a.y * b.z; acc[1][3] += a.y * b.w;
            acc[2][0] += a.z * b.x; acc[2][1] += a.z * b.y; acc[2][2] += a.z * b.z; acc[2][3] += a.z * b.w;
            acc[3][0] += a.w * b.x; acc[3][1] += a.w * b.y; acc[3][2] += a.w * b.z; acc[3][3] += a.w * b.w;
        }
        __syncthreads();
    }
    #pragma unroll
    for (int i = 0; i < 4; i++) {
        int row = m0 + tm + i;
        if (row < NN) {
            float4 o;
            float v;
            v = acc[i][0] + sb[tn];     o.x = v > 0.f ? v : expm1f(v);
            v = acc[i][1] + sb[tn + 1]; o.y = v > 0.f ? v : expm1f(v);
            v = acc[i][2] + sb[tn + 2]; o.z = v > 0.f ? v : expm1f(v);
            v = acc[i][3] + sb[tn + 3]; o.w = v > 0.f ? v : expm1f(v);
            *(float4*)&g_h1act[(size_t)row * D1 + h * HID + tn] = o;
        }
    }
}

// -------- layer 2 GEMV + coefficients (warp per node) --------
__global__ void node2_kernel(const float* __restrict__ W2,
                             const float* __restrict__ as2,
                             const float* __restrict__ ad2) {
    __shared__ float Ws[D1 * NC];   // 20 KB
    __shared__ float sas[NC], sad[NC];
    int t = threadIdx.x;
    for (int i = t; i < D1 * NC; i += 256) Ws[i] = W2[i];
    if (t < NC) { sas[t] = as2[t]; sad[t] = ad2[t]; }
    __syncthreads();
    int n = blockIdx.x * 8 + (t >> 5);
    if (n >= NN) return;
    int lane = t & 31;
    const float* hp = &g_h1act[(size_t)n * D1];
    float acc[NC];
    #pragma unroll
    for (int j = 0; j < NC; j++) acc[j] = 0.f;
    for (int c = lane; c < D1; c += 32) {
        float xv = hp[c];
        #pragma unroll
        for (int j = 0; j < NC; j++) acc[j] += xv * Ws[c * NC + j];
    }
    #pragma unroll
    for (int j = 0; j < NC; j++) acc[j] = wredsum(acc[j]);
    if (lane == 0) {
        float s = 0.f, dd = 0.f;
        #pragma unroll
        for (int j = 0; j < NC; j++) {
            g_h2[n * NC + j] = acc[j];
            s  += acc[j] * sas[j];
            dd += acc[j] * sad[j];
        }
        g_asrc2[n] = s;
        g_adst2[n] = dd;
    }
}

// -------- layer-2 edge softmax + aggregation (warp per dst, single pass) --------
__global__ void agg2_kernel(const float* __restrict__ b2) {
    int n = blockIdx.x * 8 + (threadIdx.x >> 5);
    if (n >= NN) return;
    int lane = threadIdx.x & 31;
    int beg = g_rowptr[n], end = g_rowptr[n + 1];
    float adv = g_adst2[n];
    float s = 0.f;
    float acc[NC];
    #pragma unroll
    for (int j = 0; j < NC; j++) acc[j] = 0.f;
    for (int i = beg + lane; i < end; i += 32) {
        int sn = g_csrc[i];
        float e = g_asrc2[sn] + adv;
        e = e > 0.f ? e : 0.2f * e;
        float w = __expf(e);
        s += w;
        const float* hp = &g_h2[sn * NC];
        #pragma unroll
        for (int j = 0; j < NC; j++) acc[j] += w * hp[j];
    }
    s = wredsum(s);
    #pragma unroll
    for (int j = 0; j < NC; j++) acc[j] = wredsum(acc[j]);
    if (lane == 0) {
        float inv = 1.f / (s + 1e-16f);
        #pragma unroll
        for (int j = 0; j < NC; j++)
            g_agg2[n * NC + j] = acc[j] * inv + b2[j];
    }
}

// -------- mean pooling per graph (batch is sorted) --------
__global__ void pool_kernel(const int* __restrict__ batch,
                            float* __restrict__ out) {
    int g = blockIdx.x;
    int t = threadIdx.x;
    int lo, hi;
    { int a = 0, b = NN;
      while (a < b) { int mid = (a + b) >> 1; if (batch[mid] < g) a = mid + 1; else b = mid; }
      lo = a; }
    { int a = lo, b = NN;
      while (a < b) { int mid = (a + b) >> 1; if (batch[mid] < g + 1) a = mid + 1; else b = mid; }
      hi = a; }
    __shared__ float red[NC];
    if (t < NC) red[t] = 0.f;
    __syncthreads();
    float acc[NC];
    #pragma unroll
    for (int j = 0; j < NC; j++) acc[j] = 0.f;
    for (int i = lo + t; i < hi; i += 256) {
        const float* hp = &g_agg2[i * NC];
        #pragma unroll
        for (int j = 0; j < NC; j++) acc[j] += hp[j];
    }
    #pragma unroll
    for (int j = 0; j < NC; j++) atomicAdd(&red[j], acc[j]);
    __syncthreads();
    int cnt = hi - lo;
    if (cnt < 1) cnt = 1;
    if (t < NC) out[g * NC + t] = red[t] / (float)cnt;
}

// -------- launcher --------
extern "C" void kernel_launch(void* const* d_in, const int* in_sizes, int n_in,
                              void* d_out, int out_size) {
    const float* x   = (const float*)d_in[0];
    const int*   ei  = (const int*)d_in[1];
    const int*   bat = (const int*)d_in[2];
    const float* W1  = (const float*)d_in[3];
    const float* as1 = (const float*)d_in[4];
    const float* ad1 = (const float*)d_in[5];
    const float* b1  = (const float*)d_in[6];
    const float* W2  = (const float*)d_in[7];
    const float* as2 = (const float*)d_in[8];
    const float* ad2 = (const float*)d_in[9];
    const float* b2  = (const float*)d_in[10];
    float* out = (float*)d_out;

    zero_counts_kernel<<<(NN + 255) / 256, 256>>>();
    count_kernel<<<(ET + 255) / 256, 256>>>(ei);
    va_kernel<<<HEADS, 128>>>(W1, as1, ad1);
    coefx_kernel<<<(NN + 7) / 8, 256>>>(x);
    scan_kernel<<<1, 1024>>>();
    scatter_kernel<<<(ET + 255) / 256, 256>>>(ei);

    agg1x_kernel<<<NN, 128>>>(x);
    gemmh_kernel<<<dim3(HEADS, (NN + 63) / 64), 256>>>(W1, b1);

    node2_kernel<<<(NN + 7) / 8, 256>>>(W2, as2, ad2);
    agg2_kernel<<<(NN + 7) / 8, 256>>>(b2);
    pool_kernel<<<NG, 256>>>(bat, out);
}

// round 5
// speedup vs baseline: 1.0665x; 1.0665x over previous
#include <cuda_runtime.h>
#include <math.h>

#define NN 20000
#define EE 320000
#define ET 340000      // EE + NN self loops
#define FIN 128
#define D1 512         // HEADS*HID
#define HEADS 8
#define HID 64
#define NC 10
#define NG 64

// -------- scratch (device globals; no allocations allowed) --------
__device__ float g_aggx[(size_t)NN * HEADS * FIN];  // per-head aggregated x (normalized)
__device__ float g_h1act[(size_t)NN * D1];          // elu(aggx @ W1 + b1)
__device__ float g_va[FIN * HEADS * 2];             // TRANSPOSED: [h][c], src then dst
__device__ float g_asrc1[NN * HEADS];
__device__ float g_adst1[NN * HEADS];
__device__ float g_h2[NN * NC];
__device__ float g_asrc2[NN];
__device__ float g_adst2[NN];
__device__ float g_agg2[NN * NC];
__device__ int   g_counts[NN];
__device__ int   g_rowptr[NN + 1];
__device__ int   g_wptr[NN];
__device__ int   g_csrc[ET];

__device__ __forceinline__ float wredsum(float v) {
    #pragma unroll
    for (int o = 16; o; o >>= 1) v += __shfl_xor_sync(0xffffffffu, v, o);
    return v;
}

// -------- CSR build --------
// counts start at 1: the self-loop is pre-counted and its slot is filled in scan.
__global__ void init_counts_kernel() {
    int i = blockIdx.x * blockDim.x + threadIdx.x;
    if (i < NN) g_counts[i] = 1;
}

// ILP-4: int4 loads, 4 outstanding atomics per thread
__global__ void count_kernel(const int* __restrict__ ei) {
    int i = blockIdx.x * blockDim.x + threadIdx.x;
    if (i >= EE / 4) return;
    int4 d = ((const int4*)(ei + EE))[i];
    atomicAdd(&g_counts[d.x], 1);
    atomicAdd(&g_counts[d.y], 1);
    atomicAdd(&g_counts[d.z], 1);
    atomicAdd(&g_counts[d.w], 1);
}

__global__ void scan_kernel() {
    __shared__ int sh[1024];
    int t = threadIdx.x;
    const int CH = (NN + 1023) / 1024;
    int base = t * CH;
    int s = 0;
    for (int i = 0; i < CH; i++) {
        int idx = base + i;
        if (idx < NN) s += g_counts[idx];
    }
    sh[t] = s;
    __syncthreads();
    for (int off = 1; off < 1024; off <<= 1) {
        int v = (t >= off) ? sh[t - off] : 0;
        __syncthreads();
        sh[t] += v;
        __syncthreads();
    }
    int run = sh[t] - s;
    for (int i = 0; i < CH; i++) {
        int idx = base + i;
        if (idx < NN) {
            g_rowptr[idx] = run;
            g_csrc[run]   = idx;      // self-loop occupies first slot
            g_wptr[idx]   = run + 1;  // real edges start after it
            run += g_counts[idx];
        }
    }
    if (t == 1023) g_rowptr[NN] = sh[1023];
}

__global__ void scatter_kernel(const int* __restrict__ ei) {
    int i = blockIdx.x * blockDim.x + threadIdx.x;
    if (i >= EE / 4) return;
    int4 s = ((const int4*)ei)[i];
    int4 d = ((const int4*)(ei + EE))[i];
    int p0 = atomicAdd(&g_wptr[d.x], 1);
    int p1 = atomicAdd(&g_wptr[d.y], 1);
    int p2 = atomicAdd(&g_wptr[d.z], 1);
    int p3 = atomicAdd(&g_wptr[d.w], 1);
    g_csrc[p0] = s.x;
    g_csrc[p1] = s.y;
    g_csrc[p2] = s.z;
    g_csrc[p3] = s.w;
}

// -------- va: folded attention vectors, TRANSPOSED layout [h][c] --------
// va_src[h][c] = sum_j W1[c, h*64+j]*a_src[h][j]
__global__ void va_kernel(const float* __restrict__ W1,
                          const float* __restrict__ asv,
                          const float* __restrict__ adv) {
    int h = blockIdx.x;          // 8 blocks
    int c = threadIdx.x;         // 128
    __shared__ float sa[HID], sd[HID];
    if (c < HID) { sa[c] = asv[h * HID + c]; sd[c] = adv[h * HID + c]; }
    __syncthreads();
    const float* wp = &W1[(size_t)c * D1 + h * HID];
    float s = 0.f, d = 0.f;
    #pragma unroll 8
    for (int j = 0; j < HID; j++) {
        float w = wp[j];
        s += w * sa[j];
        d += w * sd[j];
    }
    g_va[h * FIN + c] = s;
    g_va[FIN * HEADS + h * FIN + c] = d;
}

// -------- per-node attention logits (bank-conflict-free) --------
__global__ void coefx_kernel(const float* __restrict__ X) {
    __shared__ float vs[HEADS * FIN], vd[HEADS * FIN];
    int t = threadIdx.x;   // 256
    for (int i = t; i < HEADS * FIN; i += 256) {
        vs[i] = g_va[i];
        vd[i] = g_va[HEADS * FIN + i];
    }
    __syncthreads();
    int n = blockIdx.x * 8 + (t >> 5);
    if (n >= NN) return;
    int lane = t & 31;
    float4 xv = *(const float4*)&X[(size_t)n * FIN + lane * 4];
    const float4* vs4 = (const float4*)vs;
    const float4* vd4 = (const float4*)vd;
    float s[HEADS], d[HEADS];
    #pragma unroll
    for (int h = 0; h < HEADS; h++) {
        float4 a = vs4[h * 32 + lane];   // consecutive lanes -> conflict-free
        float4 b = vd4[h * 32 + lane];
        s[h] = xv.x * a.x + xv.y * a.y + xv.z * a.z + xv.w * a.w;
        d[h] = xv.x * b.x + xv.y * b.y + xv.z * b.z + xv.w * b.w;
    }
    #pragma unroll
    for (int h = 0; h < HEADS; h++) {
        s[h] = wredsum(s[h]);
        d[h] = wredsum(d[h]);
    }
    if (lane == 0) {
        *(float4*)&g_asrc1[n * 8]     = make_float4(s[0], s[1], s[2], s[3]);
        *(float4*)&g_asrc1[n * 8 + 4] = make_float4(s[4], s[5], s[6], s[7]);
        *(float4*)&g_adst1[n * 8]     = make_float4(d[0], d[1], d[2], d[3]);
        *(float4*)&g_adst1[n * 8 + 4] = make_float4(d[4], d[5], d[6], d[7]);
    }
}

// -------- layer-1 softmax-weighted aggregation of RAW x rows --------
__global__ void agg1x_kernel(const float* __restrict__ X) {
    int d = blockIdx.x;
    int t = threadIdx.x;   // 128, thread t owns channel c = t
    __shared__ float sadst[8], salpha[128], sinv[8];
    __shared__ int ssrc[16];
    int beg = g_rowptr[d];
    int deg = g_rowptr[d + 1] - beg;
    if (t < 8) sadst[t] = g_adst1[d * 8 + t];
    float acc[8];
    #pragma unroll
    for (int h = 0; h < 8; h++) acc[h] = 0.f;
    float wpart = 0.f;

    for (int base = 0; base < deg; base += 16) {
        int cn = min(16, deg - base);
        __syncthreads();
        if (t < cn) ssrc[t] = g_csrc[beg + base + t];
        if (t < cn * 8) {
            int i = t >> 3, h = t & 7;
            float e = g_asrc1[g_csrc[beg + base + i] * 8 + h] + sadst[h];
            e = e > 0.f ? e : 0.2f * e;
            float w = __expf(e);
            salpha[t] = w;
            wpart += w;
        }
        __syncthreads();
        #pragma unroll 4
        for (int i = 0; i < cn; i++) {
            float xv = X[(size_t)ssrc[i] * FIN + t];
            float4 a0 = *(const float4*)&salpha[i * 8];
            float4 a1 = *(const float4*)&salpha[i * 8 + 4];
            acc[0] += a0.x * xv; acc[1] += a0.y * xv;
            acc[2] += a0.z * xv; acc[3] += a0.w * xv;
            acc[4] += a1.x * xv; acc[5] += a1.y * xv;
            acc[6] += a1.z * xv; acc[7] += a1.w * xv;
        }
    }
    __syncthreads();
    salpha[t] = wpart;
    __syncthreads();
    if (t < 8) {
        float s = 0.f;
        #pragma unroll
        for (int j = 0; j < 16; j++) s += salpha[t + 8 * j];
        sinv[t] = 1.f / (s + 1e-16f);
    }
    __syncthreads();
    float* op = &g_aggx[(size_t)d * (HEADS * FIN)];
    #pragma unroll
    for (int h = 0; h < 8; h++) op[h * FIN + t] = acc[h] * sinv[h];
}

// -------- per-head GEMM: h1act[:, h*64:(h+1)*64] = elu(aggx[:,h,:] @ W1[:, h*64:..] + b1) --------
__global__ void gemmh_kernel(const float* __restrict__ W1,
                             const float* __restrict__ b1) {
    __shared__ float As[64][68];
    __shared__ float Bs[64][64];
    __shared__ float sb[64];
    int t = threadIdx.x;
    int h = blockIdx.x;
    int m0 = blockIdx.y * 64;
    if (t < 64) sb[t] = b1[h * HID + t];
    int tm = (t >> 4) << 2;
    int tn = (t & 15) << 2;
    float acc[4][4];
    #pragma unroll
    for (int i = 0; i < 4; i++)
        #pragma unroll
        for (int j = 0; j < 4; j++) acc[i][j] = 0.f;

    for (int k0 = 0; k0 < FIN; k0 += 64) {
        int kk = t & 63;
        #pragma unroll
        for (int p = 0; p < 16; p++) {
            int rr = (t >> 6) + p * 4;
            int row = m0 + rr;
            float v = (row < NN)
                ? g_aggx[(size_t)row * (HEADS * FIN) + h * FIN + k0 + kk] : 0.f;
            As[kk][rr] = v;
        }
        #pragma unroll
        for (int p = 0; p < 4; p++) {
            int id = t + p * 256;
            int bk = id >> 4, nv = id & 15;
            float4 v = *(const float4*)&W1[(size_t)(k0 + bk) * D1 + h * HID + (nv << 2)];
            *(float4*)&Bs[bk][nv << 2] = v;
        }
        __syncthreads();
        #pragma unroll 16
        for (int k = 0; k < 64; k++) {
            float4 a = *(const float4*)&As[k][tm];
            float4 b = *(const float4*)&Bs[k][tn];
            acc[0][0] += a.x * b.x; acc[0][1] += a.x * b.y; acc[0][2] += a.x * b.z; acc[0][3] += a.x * b.w;
            acc[1][0] += a.y * b.x; acc[1][1] += a.y * b.y; acc[1][2] += a.y * b.z; acc[1][3] += a.y * b.w;
            acc[2][0] += a.z * b.x; acc[2][1] += a.z * b.y; acc[2][2] += a.z * b.z; acc[2][3] += a.z * b.w;
            acc[3][0] += a.w * b.x; acc[3][1] += a.w * b.y; acc[3][2] += a.w * b.z; acc[3][3] += a.w * b.w;
        }
        __syncthreads();
    }
    #pragma unroll
    for (int i = 0; i < 4; i++) {
        int row = m0 + tm + i;
        if (row < NN) {
            float4 o;
            float v;
            v = acc[i][0] + sb[tn];     o.x = v > 0.f ? v : expm1f(v);
            v = acc[i][1] + sb[tn + 1]; o.y = v > 0.f ? v : expm1f(v);
            v = acc[i][2] + sb[tn + 2]; o.z = v > 0.f ? v : expm1f(v);
            v = acc[i][3] + sb[tn + 3]; o.w = v > 0.f ? v : expm1f(v);
            *(float4*)&g_h1act[(size_t)row * D1 + h * HID + tn] = o;
        }
    }
}

// -------- layer 2 GEMV + coefficients (warp per node, transposed W2 in smem) --------
__global__ void node2_kernel(const float* __restrict__ W2,
                             const float* __restrict__ as2,
                             const float* __restrict__ ad2) {
    __shared__ float Ws[NC * D1];   // [j][c] transposed, 20 KB
    __shared__ float sas[NC], sad[NC];
    int t = threadIdx.x;
    for (int i = t; i < D1 * NC; i += 256) {
        int c = i / NC, j = i - c * NC;
        Ws[j * D1 + c] = W2[i];
    }
    if (t < NC) { sas[t] = as2[t]; sad[t] = ad2[t]; }
    __syncthreads();
    int n = blockIdx.x * 8 + (t >> 5);
    if (n >= NN) return;
    int lane = t & 31;
    const float* hp = &g_h1act[(size_t)n * D1];
    float acc[NC];
    #pragma unroll
    for (int j = 0; j < NC; j++) acc[j] = 0.f;
    for (int c = lane; c < D1; c += 32) {
        float xv = hp[c];
        #pragma unroll
        for (int j = 0; j < NC; j++) acc[j] += xv * Ws[j * D1 + c];  // conflict-free
    }
    #pragma unroll
    for (int j = 0; j < NC; j++) acc[j] = wredsum(acc[j]);
    if (lane == 0) {
        float s = 0.f, dd = 0.f;
        #pragma unroll
        for (int j = 0; j < NC; j++) {
            g_h2[n * NC + j] = acc[j];
            s  += acc[j] * sas[j];
            dd += acc[j] * sad[j];
        }
        g_asrc2[n] = s;
        g_adst2[n] = dd;
    }
}

// -------- layer-2 edge softmax + aggregation (warp per dst, single pass) --------
__global__ void agg2_kernel(const float* __restrict__ b2) {
    int n = blockIdx.x * 8 + (threadIdx.x >> 5);
    if (n >= NN) return;
    int lane = threadIdx.x & 31;
    int beg = g_rowptr[n], end = g_rowptr[n + 1];
    float adv = g_adst2[n];
    float s = 0.f;
    float acc[NC];
    #pragma unroll
    for (int j = 0; j < NC; j++) acc[j] = 0.f;
    for (int i = beg + lane; i < end; i += 32) {
        int sn = g_csrc[i];
        float e = g_asrc2[sn] + adv;
        e = e > 0.f ? e : 0.2f * e;
        float w = __expf(e);
        s += w;
        const float* hp = &g_h2[sn * NC];
        #pragma unroll
        for (int j = 0; j < NC; j++) acc[j] += w * hp[j];
    }
    s = wredsum(s);
    #pragma unroll
    for (int j = 0; j < NC; j++) acc[j] = wredsum(acc[j]);
    if (lane == 0) {
        float inv = 1.f / (s + 1e-16f);
        #pragma unroll
        for (int j = 0; j < NC; j++)
            g_agg2[n * NC + j] = acc[j] * inv + b2[j];
    }
}

// -------- mean pooling per graph (batch is sorted) --------
__global__ void pool_kernel(const int* __restrict__ batch,
                            float* __restrict__ out) {
    int g = blockIdx.x;
    int t = threadIdx.x;
    int lo, hi;
    { int a = 0, b = NN;
      while (a < b) { int mid = (a + b) >> 1; if (batch[mid] < g) a = mid + 1; else b = mid; }
      lo = a; }
    { int a = lo, b = NN;
      while (a < b) { int mid = (a + b) >> 1; if (batch[mid] < g + 1) a = mid + 1; else b = mid; }
      hi = a; }
    __shared__ float red[NC];
    if (t < NC) red[t] = 0.f;
    __syncthreads();
    float acc[NC];
    #pragma unroll
    for (int j = 0; j < NC; j++) acc[j] = 0.f;
    for (int i = lo + t; i < hi; i += 256) {
        const float* hp = &g_agg2[i * NC];
        #pragma unroll
        for (int j = 0; j < NC; j++) acc[j] += hp[j];
    }
    #pragma unroll
    for (int j = 0; j < NC; j++) atomicAdd(&red[j], acc[j]);
    __syncthreads();
    int cnt = hi - lo;
    if (cnt < 1) cnt = 1;
    if (t < NC) out[g * NC + t] = red[t] / (float)cnt;
}

// -------- launcher --------
extern "C" void kernel_launch(void* const* d_in, const int* in_sizes, int n_in,
                              void* d_out, int out_size) {
    const float* x   = (const float*)d_in[0];
    const int*   ei  = (const int*)d_in[1];
    const int*   bat = (const int*)d_in[2];
    const float* W1  = (const float*)d_in[3];
    const float* as1 = (const float*)d_in[4];
    const float* ad1 = (const float*)d_in[5];
    const float* b1  = (const float*)d_in[6];
    const float* W2  = (const float*)d_in[7];
    const float* as2 = (const float*)d_in[8];
    const float* ad2 = (const float*)d_in[9];
    const float* b2  = (const float*)d_in[10];
    float* out = (float*)d_out;

    init_counts_kernel<<<(NN + 255) / 256, 256>>>();
    count_kernel<<<(EE / 4 + 255) / 256, 256>>>(ei);
    va_kernel<<<HEADS, 128>>>(W1, as1, ad1);
    coefx_kernel<<<(NN + 7) / 8, 256>>>(x);
    scan_kernel<<<1, 1024>>>();
    scatter_kernel<<<(EE / 4 + 255) / 256, 256>>>(ei);

    agg1x_kernel<<<NN, 128>>>(x);
    gemmh_kernel<<<dim3(HEADS, (NN + 63) / 64), 256>>>(W1, b1);

    node2_kernel<<<(NN + 7) / 8, 256>>>(W2, as2, ad2);
    agg2_kernel<<<(NN + 7) / 8, 256>>>(b2);
    pool_kernel<<<NG, 256>>>(bat, out);
}